// round 8
// baseline (speedup 1.0000x reference)
#include <cuda_runtime.h>

// ---------------------------------------------------------------------------
// LSTMModel: 4-layer LSTM (H=50) over B=1024, T=512, IN=7, + FC(25) + FC(1).
// R7: R4's proven gate phase (scalar FFMA, [k][b] float4 broadcast, NB=4,
// 256 CTAs, 2/SM) + R5's proven fused update (in-quad shfl 4x4 transpose,
// c in registers) -> ONE __syncthreads per step, no sh_g round-trip.
// Thread 4u+p owns gate p*50+u; after transpose lane p updates batch row p.
// Warp 7 prefetches next-step x. h/x unified in double-buffered sh_in.
// ---------------------------------------------------------------------------

#define TT  512
#define BB  1024
#define HH  50
#define GG  200
#define NB  4
#define NCTA (BB / NB)    // 256
#define IN0 7
#define FC1 25

__device__ float g_bufA[TT * BB * HH];
__device__ float g_bufB[TT * BB * HH];
__device__ float g_xT[TT * BB * IN0];

__device__ __forceinline__ float sigmf(float x) {
    return __fdividef(1.0f, 1.0f + __expf(-x));
}
__device__ __forceinline__ float tanhfast(float x) {
    float e = __expf(2.0f * x);
    return 1.0f - __fdividef(2.0f, e + 1.0f);
}

// ---------------------------------------------------------------------------
__global__ void transpose_x_kernel(const float* __restrict__ x) {
    int idx = blockIdx.x * blockDim.x + threadIdx.x;
    if (idx < BB * TT * IN0) {
        int k = idx % IN0;
        int t = (idx / IN0) % TT;
        int b = idx / (IN0 * TT);
        g_xT[(t * BB + b) * IN0 + k] = x[idx];
    }
}

// ---------------------------------------------------------------------------
// One LSTM layer over the whole sequence for a 4-row batch tile.
// ---------------------------------------------------------------------------
template <int KIN>
__global__ void __launch_bounds__(256, 2) lstm_layer_kernel(
    int src, int dst,
    const float* __restrict__ Wih,   // [GG][KIN]
    const float* __restrict__ Whh,   // [GG][HH]
    const float* __restrict__ bih,
    const float* __restrict__ bhh)
{
    constexpr int K = KIN + HH;      // 57 or 100

    const float* __restrict__ in_seq =
        (src == 0) ? g_xT : ((src == 1) ? g_bufA : g_bufB);
    float* __restrict__ out_seq = (dst == 1) ? g_bufA : g_bufB;

    // unified input: rows 0..KIN-1 = x(t), rows KIN..K-1 = h(t); double-buffered
    __shared__ __align__(16) float sh_in[2][K][NB];

    const int tid = threadIdx.x;
    const int b0  = blockIdx.x * NB;

    // thread 4u+p owns gate g = p*50 + u  (p = gate type: i,f,g,o)
    const int p  = tid & 3;
    const int u  = tid >> 2;
    const int uc = (u < HH) ? u : (HH - 1);   // clamp for dummy threads 200..223
    const int g  = p * HH + uc;
    const bool is_real = (tid < GG);

    // ---- per-thread weight row in registers (warps 0..6 all run gate path)
    float wih[KIN], whh[HH];
    float bg = 0.0f;
    if (tid < 224) {
#pragma unroll
        for (int k = 0; k < KIN; k++) wih[k] = Wih[g * KIN + k];
#pragma unroll
        for (int k = 0; k < HH; k++) whh[k] = Whh[g * HH + k];
        bg = bih[g] + bhh[g];
    }

    float creg = 0.0f;   // cell state for (unit u, batch row p)

    // ---- init: zero both buffers (h0 = 0), stage x(t=0) into buf 0
    for (int i = tid; i < 2 * K * NB; i += 256)
        (&sh_in[0][0][0])[i] = 0.0f;
    __syncthreads();
    for (int i = tid; i < KIN * NB; i += 256) {
        int b = i % NB, k = i / NB;
        sh_in[0][k][b] = in_seq[(b0 + b) * KIN + k];
    }
    __syncthreads();

    int buf = 0;
    for (int t = 0; t < TT; t++) {
        const bool has_next = (t + 1 < TT);

        if (tid >= 224) {
            // ---- prefetch warp: load + park next-step x into other buffer
            if (has_next) {
                // KIN*NB <= 200; up to 7 elements per thread (32 threads)
                constexpr int PF = (KIN * NB + 31) / 32;
                float pf[PF];
#pragma unroll
                for (int j = 0; j < PF; j++) {
                    int i = (tid - 224) + j * 32;
                    if (i < KIN * NB) {
                        int b = i % NB, k = i / NB;
                        pf[j] = in_seq[((t + 1) * BB + b0 + b) * KIN + k];
                    }
                }
#pragma unroll
                for (int j = 0; j < PF; j++) {
                    int i = (tid - 224) + j * 32;
                    if (i < KIN * NB) {
                        int b = i % NB, k = i / NB;
                        sh_in[buf ^ 1][k][b] = pf[j];
                    }
                }
            }
        } else {
            // ---- gate phase (R4 layout): 4 acc chains over [k][b] broadcast
            float a0 = bg, a1 = bg, a2 = bg, a3 = bg;
#pragma unroll
            for (int k = 0; k < KIN; k++) {
                float w = wih[k];
                float4 xv = *(const float4*)&sh_in[buf][k][0];
                a0 += w * xv.x; a1 += w * xv.y;
                a2 += w * xv.z; a3 += w * xv.w;
            }
#pragma unroll
            for (int k = 0; k < HH; k++) {
                float w = whh[k];
                float4 hv = *(const float4*)&sh_in[buf][KIN + k][0];
                a0 += w * hv.x; a1 += w * hv.y;
                a2 += w * hv.z; a3 += w * hv.w;
            }

            // ---- in-quad 4x4 transpose: after, a[e] = gate type e of row p
            float a[NB] = {a0, a1, a2, a3};
            {
                float tmp[NB];
#pragma unroll
                for (int e = 0; e < NB; e++)
                    tmp[e] = __shfl_xor_sync(0xffffffffu, a[e ^ 1], 1);
#pragma unroll
                for (int e = 0; e < NB; e++)
                    if ((e ^ p) & 1) a[e] = tmp[e];
#pragma unroll
                for (int e = 0; e < NB; e++)
                    tmp[e] = __shfl_xor_sync(0xffffffffu, a[e ^ 2], 2);
#pragma unroll
                for (int e = 0; e < NB; e++)
                    if ((e ^ p) & 2) a[e] = tmp[e];
            }

            // ---- fused update: this thread owns (unit u, batch row p)
            float ig = sigmf(a[0]);
            float fg = sigmf(a[1]);
            float gg = tanhfast(a[2]);
            float og = sigmf(a[3]);
            creg = fg * creg + ig * gg;
            float h = og * tanhfast(creg);
            if (is_real) {
                sh_in[buf ^ 1][KIN + u][p] = h;
                out_seq[(t * BB + b0 + p) * HH + u] = h;
            }
        }
        __syncthreads();
        buf ^= 1;
    }
}

// ---------------------------------------------------------------------------
__global__ void fc_head_kernel(int src,
                               const float* __restrict__ W1,
                               const float* __restrict__ b1,
                               const float* __restrict__ W2,
                               const float* __restrict__ b2,
                               float* __restrict__ out)
{
    const float* __restrict__ hseq = (src == 1) ? g_bufA : g_bufB;
    __shared__ float sW1[FC1 * HH];
    __shared__ float sW2[FC1];
    __shared__ float sb1[FC1];

    int tid = threadIdx.x;
    for (int i = tid; i < FC1 * HH; i += 256) sW1[i] = W1[i];
    if (tid < FC1) { sW2[tid] = W2[tid]; sb1[tid] = b1[tid]; }
    __syncthreads();

    int b = blockIdx.x * blockDim.x + tid;
    if (b < BB) {
        const float* h = &hseq[((TT - 1) * BB + b) * HH];
        float hreg[HH];
#pragma unroll
        for (int k = 0; k < HH; k++) hreg[k] = h[k];
        float o = b2[0];
#pragma unroll
        for (int j = 0; j < FC1; j++) {
            float a = sb1[j];
#pragma unroll
            for (int k = 0; k < HH; k++) a += sW1[j * HH + k] * hreg[k];
            o += sW2[j] * fmaxf(a, 0.0f);
        }
        out[b] = o;
    }
}

// ---------------------------------------------------------------------------
extern "C" void kernel_launch(void* const* d_in, const int* in_sizes, int n_in,
                              void* d_out, int out_size)
{
    const float* x    = (const float*)d_in[0];
    const float* Wih0 = (const float*)d_in[1];
    const float* Whh0 = (const float*)d_in[2];
    const float* bih0 = (const float*)d_in[3];
    const float* bhh0 = (const float*)d_in[4];
    const float* Wih1 = (const float*)d_in[5];
    const float* Whh1 = (const float*)d_in[6];
    const float* bih1 = (const float*)d_in[7];
    const float* bhh1 = (const float*)d_in[8];
    const float* Wih2 = (const float*)d_in[9];
    const float* Whh2 = (const float*)d_in[10];
    const float* bih2 = (const float*)d_in[11];
    const float* bhh2 = (const float*)d_in[12];
    const float* Wih3 = (const float*)d_in[13];
    const float* Whh3 = (const float*)d_in[14];
    const float* bih3 = (const float*)d_in[15];
    const float* bhh3 = (const float*)d_in[16];
    const float* W1   = (const float*)d_in[17];
    const float* b1   = (const float*)d_in[18];
    const float* W2   = (const float*)d_in[19];
    const float* b2   = (const float*)d_in[20];
    float* out = (float*)d_out;

    {
        int total = BB * TT * IN0;
        transpose_x_kernel<<<(total + 255) / 256, 256>>>(x);
    }
    lstm_layer_kernel<IN0><<<NCTA, 256>>>(0, 1, Wih0, Whh0, bih0, bhh0);
    lstm_layer_kernel<HH> <<<NCTA, 256>>>(1, 2, Wih1, Whh1, bih1, bhh1);
    lstm_layer_kernel<HH> <<<NCTA, 256>>>(2, 1, Wih2, Whh2, bih2, bhh2);
    lstm_layer_kernel<HH> <<<NCTA, 256>>>(1, 2, Wih3, Whh3, bih3, bhh3);
    fc_head_kernel<<<(BB + 255) / 256, 256>>>(2, W1, b1, W2, b2, out);
}

// round 9
// speedup vs baseline: 1.1346x; 1.1346x over previous
#include <cuda_runtime.h>

// ---------------------------------------------------------------------------
// LSTMModel: 4-layer LSTM (H=50) over B=1024, T=512, IN=7, + FC(25) + FC(1).
// R8: per layer, (1) xp GEMM precomputes the input-part xp = Wih @ in for the
// whole sequence (parallel, batch-paired fma.rn.f32x2, weights pre-dup'd in
// regs), stored packed so (2) the recurrent kernel loads xp straight into its
// packed accumulators and runs only the Whh part: per k = 1 LDS.128 + 2 FMA2
// (0.25 FMA2-instr/MAC). Whh dup'd in regs (100 regs) -- enabled by removing
// Wih from the loop. NB=4, 256 CTAs, 2/SM. Update phase identical to R4.
// ---------------------------------------------------------------------------

#define TT  512
#define BB  1024
#define HH  50
#define GG  200
#define NB  4
#define NCTA (BB / NB)    // 256
#define IN0 7
#define FC1 25

__device__ float g_bufA[TT * BB * HH];
__device__ float g_bufB[TT * BB * HH];
// xp scratch: [t][ct][g][b'] packed, 512*256*200*4 floats (~420 MB)
__device__ float g_xp[(size_t)TT * NCTA * GG * NB];

__device__ __forceinline__ float sigmf(float x) {
    return __fdividef(1.0f, 1.0f + __expf(-x));
}
__device__ __forceinline__ float tanhfast(float x) {
    float e = __expf(2.0f * x);
    return 1.0f - __fdividef(2.0f, e + 1.0f);
}

#define FMA2(acc, w, h) \
    asm("fma.rn.f32x2 %0, %1, %2, %0;" : "+l"(acc) : "l"(w), "l"(h))
#define ADD2(out, a, b) \
    asm("add.rn.f32x2 %0, %1, %2;" : "=l"(out) : "l"(a), "l"(b))
#define DUP2(out, w) \
    asm("mov.b64 %0, {%1, %1};" : "=l"(out) : "f"(w))

// ---------------------------------------------------------------------------
// xp GEMM: xp[t][ct][g][b'] = sum_k in[...] * Wih[g][k]
// KIN==IN0: in = x, layout [B][T][IN0]; else in = h-seq, layout [T][B][HH].
// Grid: NCTA * (TT/TCH) CTAs; CTA = (ct, t-chunk). 256 threads.
// ---------------------------------------------------------------------------
template <int KIN>
__global__ void __launch_bounds__(256, 2) xp_gemm_kernel(
    const float* __restrict__ in,
    const float* __restrict__ Wih)   // [GG][KIN]
{
    constexpr int TCH = 64;

    __shared__ __align__(16) float sh[2][KIN][NB];

    const int tid = threadIdx.x;
    const int ct  = blockIdx.x & (NCTA - 1);
    const int t0  = (int)(blockIdx.x >> 8) * TCH;
    const int b0  = ct * NB;

    // dup'd weight row for gate g (clamped for lanes 200..223)
    const int g = (tid < GG) ? tid : (GG - 1);
    unsigned long long wd[KIN];
    if (tid < 224) {
#pragma unroll
        for (int k = 0; k < KIN; k++) DUP2(wd[k], Wih[g * KIN + k]);
    }

    // stager mapping: thread i < KIN*NB loads (k = i>>2, b = i&3)
    const int sk = tid >> 2, sb = tid & 3;
    const bool stager = (tid < KIN * NB);

    if (stager) {
        sh[0][sk][sb] = (KIN == IN0)
            ? in[(size_t)(b0 + sb) * TT * IN0 + (size_t)t0 * IN0 + sk]
            : in[((size_t)t0 * BB + b0 + sb) * KIN + sk];
    }
    __syncthreads();

    int buf = 0;
    for (int t = t0; t < t0 + TCH; t++) {
        const bool hn = (t + 1 < t0 + TCH);
        float pf = 0.0f;
        if (stager && hn) {
            pf = (KIN == IN0)
               ? in[(size_t)(b0 + sb) * TT * IN0 + (size_t)(t + 1) * IN0 + sk]
               : in[((size_t)(t + 1) * BB + b0 + sb) * KIN + sk];
        }

        if (tid < 224) {
            unsigned long long a0 = 0ull, a1 = 0ull;
#pragma unroll
            for (int k = 0; k < KIN; k++) {
                ulonglong2 hv = *(const ulonglong2*)&sh[buf][k][0];
                FMA2(a0, wd[k], hv.x);
                FMA2(a1, wd[k], hv.y);
            }
            if (tid < GG) {
                ulonglong2 o;
                o.x = a0; o.y = a1;
                *(ulonglong2*)&g_xp[(((size_t)t * NCTA + ct) * GG + tid) * NB] = o;
            }
        }
        if (stager && hn) sh[buf ^ 1][sk][sb] = pf;
        __syncthreads();
        buf ^= 1;
    }
}

// ---------------------------------------------------------------------------
// Recurrent kernel: gates = xp(t) + Whh @ h(t-1) + bias; cell update.
// ---------------------------------------------------------------------------
__global__ void __launch_bounds__(256, 2) lstm_rec_kernel(
    int dst,
    const float* __restrict__ Whh,   // [GG][HH]
    const float* __restrict__ bih,
    const float* __restrict__ bhh)
{
    float* __restrict__ out_seq = (dst == 1) ? g_bufA : g_bufB;

    __shared__ __align__(16) float sh_h[HH][NB];
    __shared__ __align__(16) float sh_g[GG][NB];

    const int tid = threadIdx.x;
    const int ct  = blockIdx.x;
    const int b0  = ct * NB;

    // dup'd Whh row + dup'd bias for gate g (clamped for lanes 200..223)
    const int g = (tid < GG) ? tid : (GG - 1);
    unsigned long long wd[HH];
    unsigned long long bgd = 0ull;
    if (tid < 224) {
#pragma unroll
        for (int k = 0; k < HH; k++) DUP2(wd[k], Whh[g * HH + k]);
        DUP2(bgd, bih[g] + bhh[g]);
    }

    // update-thread state: tid<200 owns (jj = tid>>2, row bu = tid&3)
    const int jj = tid >> 2;
    const int bu = tid & 3;
    float creg = 0.0f;

    // h0 = 0
    for (int i = tid; i < HH * NB; i += 256)
        (&sh_h[0][0])[i] = 0.0f;
    __syncthreads();

    // prefetch xp(t=0) into registers
    ulonglong2 xpr;
    if (tid < 224)
        xpr = *(const ulonglong2*)&g_xp[(((size_t)0 * NCTA + ct) * GG + g) * NB];

    for (int t = 0; t < TT; t++) {
        if (tid < 224) {
            unsigned long long a0 = xpr.x, a1 = xpr.y;   // acc init = xp(t)
            if (t + 1 < TT)                               // prefetch xp(t+1)
                xpr = *(const ulonglong2*)
                    &g_xp[(((size_t)(t + 1) * NCTA + ct) * GG + g) * NB];
#pragma unroll
            for (int k = 0; k < HH; k++) {
                ulonglong2 hv = *(const ulonglong2*)&sh_h[k][0];
                FMA2(a0, wd[k], hv.x);
                FMA2(a1, wd[k], hv.y);
            }
            ADD2(a0, a0, bgd);
            ADD2(a1, a1, bgd);
            if (tid < GG) {
                ulonglong2 o;
                o.x = a0; o.y = a1;
                *(ulonglong2*)&sh_g[tid][0] = o;
            }
        }
        __syncthreads();

        if (tid < GG) {
            float ig = sigmf(sh_g[jj][bu]);
            float fg = sigmf(sh_g[HH + jj][bu]);
            float gg = tanhfast(sh_g[2 * HH + jj][bu]);
            float og = sigmf(sh_g[3 * HH + jj][bu]);
            creg = fg * creg + ig * gg;
            float h = og * tanhfast(creg);
            sh_h[jj][bu] = h;
            out_seq[((size_t)t * BB + b0 + bu) * HH + jj] = h;
        }
        __syncthreads();
    }
}

// ---------------------------------------------------------------------------
__global__ void fc_head_kernel(int src,
                               const float* __restrict__ W1,
                               const float* __restrict__ b1,
                               const float* __restrict__ W2,
                               const float* __restrict__ b2,
                               float* __restrict__ out)
{
    const float* __restrict__ hseq = (src == 1) ? g_bufA : g_bufB;
    __shared__ float sW1[FC1 * HH];
    __shared__ float sW2[FC1];
    __shared__ float sb1[FC1];

    int tid = threadIdx.x;
    for (int i = tid; i < FC1 * HH; i += 256) sW1[i] = W1[i];
    if (tid < FC1) { sW2[tid] = W2[tid]; sb1[tid] = b1[tid]; }
    __syncthreads();

    int b = blockIdx.x * blockDim.x + tid;
    if (b < BB) {
        const float* h = &hseq[((size_t)(TT - 1) * BB + b) * HH];
        float hreg[HH];
#pragma unroll
        for (int k = 0; k < HH; k++) hreg[k] = h[k];
        float o = b2[0];
#pragma unroll
        for (int j = 0; j < FC1; j++) {
            float a = sb1[j];
#pragma unroll
            for (int k = 0; k < HH; k++) a += sW1[j * HH + k] * hreg[k];
            o += sW2[j] * fmaxf(a, 0.0f);
        }
        out[b] = o;
    }
}

// ---------------------------------------------------------------------------
extern "C" void kernel_launch(void* const* d_in, const int* in_sizes, int n_in,
                              void* d_out, int out_size)
{
    const float* x    = (const float*)d_in[0];
    const float* Wih0 = (const float*)d_in[1];
    const float* Whh0 = (const float*)d_in[2];
    const float* bih0 = (const float*)d_in[3];
    const float* bhh0 = (const float*)d_in[4];
    const float* Wih1 = (const float*)d_in[5];
    const float* Whh1 = (const float*)d_in[6];
    const float* bih1 = (const float*)d_in[7];
    const float* bhh1 = (const float*)d_in[8];
    const float* Wih2 = (const float*)d_in[9];
    const float* Whh2 = (const float*)d_in[10];
    const float* bih2 = (const float*)d_in[11];
    const float* bhh2 = (const float*)d_in[12];
    const float* Wih3 = (const float*)d_in[13];
    const float* Whh3 = (const float*)d_in[14];
    const float* bih3 = (const float*)d_in[15];
    const float* bhh3 = (const float*)d_in[16];
    const float* W1   = (const float*)d_in[17];
    const float* b1   = (const float*)d_in[18];
    const float* W2   = (const float*)d_in[19];
    const float* b2   = (const float*)d_in[20];
    float* out = (float*)d_out;

    const int gemm_grid = NCTA * (TT / 64);   // 2048

    // resolve buffer device pointers for GEMM input (host-side symbol lookup
    // is not allowed in capture; use the fixed ping-pong via kernel args)
    // layer0: x -> xp; rec -> bufA
    xp_gemm_kernel<IN0><<<gemm_grid, 256>>>(x, Wih0);
    lstm_rec_kernel<<<NCTA, 256>>>(1, Whh0, bih0, bhh0);

    // layer1: bufA -> xp; rec -> bufB
    {
        static float* pA = nullptr;
        // cudaGetSymbolAddress is not graph-unsafe (host-side, no alloc/sync)
        if (!pA) cudaGetSymbolAddress((void**)&pA, g_bufA);
        xp_gemm_kernel<HH><<<gemm_grid, 256>>>(pA, Wih1);
    }
    lstm_rec_kernel<<<NCTA, 256>>>(2, Whh1, bih1, bhh1);

    // layer2: bufB -> xp; rec -> bufA
    {
        static float* pB = nullptr;
        if (!pB) cudaGetSymbolAddress((void**)&pB, g_bufB);
        xp_gemm_kernel<HH><<<gemm_grid, 256>>>(pB, Wih2);
    }
    lstm_rec_kernel<<<NCTA, 256>>>(1, Whh2, bih2, bhh2);

    // layer3: bufA -> xp; rec -> bufB
    {
        static float* pA2 = nullptr;
        if (!pA2) cudaGetSymbolAddress((void**)&pA2, g_bufA);
        xp_gemm_kernel<HH><<<gemm_grid, 256>>>(pA2, Wih3);
    }
    lstm_rec_kernel<<<NCTA, 256>>>(2, Whh3, bih3, bhh3);

    fc_head_kernel<<<(BB + 255) / 256, 256>>>(2, W1, b1, W2, b2, out);
}